// round 12
// baseline (speedup 1.0000x reference)
#include <cuda_runtime.h>
#include <cuda_fp16.h>
#include <cstdint>

// ===========================================================================
// EGNN layer. Edge-MLP stage 1 eliminated algebraically:
//   ef@eW1 = P1[row] + P2[col] + dist*w256 + attr*w257  (P1,P2 per-node).
// Remaining edge GEMMs (eW2, cW1, iW1) on mma.sync fp16 2-pass hi/lo split.
// vel MLP folded into the per-node precompute. Node MLP scalar fp32.
// ===========================================================================

#define MAXN 50016
__device__ float  g_mi[(size_t)MAXN * 128];
__device__ float4 g_agg[MAXN];
__device__ float  g_p1[(size_t)MAXN * 128];
__device__ float  g_p2[(size_t)MAXN * 128];
__device__ float  g_vel[MAXN];
// fp16 W^T images, row stride 272B: e2,c1 (34816), i1 (17408), e1a,e1b,v1 (34816)
__device__ __align__(16) unsigned char g_wimg[191488];

#define IMG_E2  0
#define IMG_C1  34816
#define IMG_I1  69632
#define IMG_E1A 87040
#define IMG_E1B 121856
#define IMG_V1  156672
#define BROW    272

// ---- smem layout (bytes), 113280 total -> 2 CTAs/SM ----
#define SA_HI   0
#define SA_LO   34816
#define SB      69632
#define SCST    104448       // 928 floats
#define SXDA    108160       // 128*8 floats
#define SRIDX   112256
#define SCIDX   112768
#define E_SMEM  113280

__device__ __forceinline__ uint32_t smem_u32(const void* p) {
    uint32_t a;
    asm("{ .reg .u64 t; cvta.to.shared.u64 t, %1; cvt.u32.u64 %0, t; }" : "=r"(a) : "l"(p));
    return a;
}
__device__ __forceinline__ void ldm4(uint32_t r[4], uint32_t addr) {
    asm volatile("ldmatrix.sync.aligned.m8n8.x4.shared.b16 {%0,%1,%2,%3}, [%4];"
        : "=r"(r[0]), "=r"(r[1]), "=r"(r[2]), "=r"(r[3]) : "r"(addr));
}
__device__ __forceinline__ void mma16816(float4& d, const uint32_t a[4], uint32_t b0, uint32_t b1) {
    asm volatile("mma.sync.aligned.m16n8k16.row.col.f32.f16.f16.f32 "
        "{%0,%1,%2,%3}, {%4,%5,%6,%7}, {%8,%9}, {%0,%1,%2,%3};"
        : "+f"(d.x), "+f"(d.y), "+f"(d.z), "+f"(d.w)
        : "r"(a[0]), "r"(a[1]), "r"(a[2]), "r"(a[3]), "r"(b0), "r"(b1));
}
#define CP16(dst, src) \
    asm volatile("cp.async.cg.shared.global [%0], [%1], 16;" :: "r"(dst), "l"(src))
#define CP_COMMIT() asm volatile("cp.async.commit_group;" ::: "memory")
#define CP_WAIT(n)  asm volatile("cp.async.wait_group %0;" :: "n"(n) : "memory")

// ---- MUFU-free silu ----
__device__ __forceinline__ float fexp_neg(float v) {
    float t = fminf(fmaxf(v, -30.f), 30.f) * -1.44269504f;
    float r = t + 12582912.f;
    int   k = __float_as_int(r) - 0x4B400000;
    float f = t - (r - 12582912.f);
    float g = f * 0.69314718f;
    float p = 1.f + g * (1.f + g * (0.5f + g * (0.16666667f + g * (0.041666667f
            + g * (8.3333333e-3f + g * 1.3888889e-3f)))));
    return p * __int_as_float((k + 127) << 23);
}
__device__ __forceinline__ float frcp(float d) {
    float y = __int_as_float(0x7EF311C3 - __float_as_int(d));
    y = y * (2.f - d * y); y = y * (2.f - d * y); y = y * (2.f - d * y);
    return y;
}
__device__ __forceinline__ float fsig(float v)  { return frcp(1.f + fexp_neg(v)); }
__device__ __forceinline__ float siluf(float v) { return v * fsig(v); }

__global__ void prep_weights(const float* __restrict__ eW1, const float* __restrict__ eW2,
                             const float* __restrict__ cW1, const float* __restrict__ iW1,
                             const float* __restrict__ vW1) {
    int i = blockIdx.x * blockDim.x + threadIdx.x;
    int base, n, k; float w;
    if (i < 16384) {
        k = i >> 7; n = i & 127; base = IMG_E2; w = eW2[k * 128 + n];
    } else if (i < 32768) {
        int j = i - 16384; k = j >> 7; n = j & 127; base = IMG_C1; w = cW1[k * 128 + n];
    } else if (i < 40960) {
        int j = i - 32768; k = j >> 6; n = j & 63; base = IMG_I1; w = iW1[k * 64 + n];
    } else if (i < 57344) {
        int j = i - 40960; k = j >> 7; n = j & 127; base = IMG_E1A; w = eW1[k * 128 + n];
    } else if (i < 73728) {
        int j = i - 57344; k = j >> 7; n = j & 127; base = IMG_E1B; w = eW1[(128 + k) * 128 + n];
    } else if (i < 90112) {
        int j = i - 73728; k = j >> 7; n = j & 127; base = IMG_V1; w = vW1[k * 128 + n];
    } else return;
    *(__half*)(g_wimg + base + n * BROW + k * 2) = __float2half(w);
}

__global__ void egnn_zero_kernel(int N) {
    int total = N * 32;
    for (int i = blockIdx.x * blockDim.x + threadIdx.x; i < total + N; i += gridDim.x * blockDim.x) {
        if (i < total) ((float4*)g_mi)[i] = make_float4(0.f, 0.f, 0.f, 0.f);
        else           g_agg[i - total]   = make_float4(0.f, 0.f, 0.f, 0.f);
    }
}

// 2-pass split GEMM: acc[NT] += (Ahi+Alo)[16,128] @ B[128, NT*8]
template <int NT>
__device__ __forceinline__ void gemm2p(float4* acc, uint32_t aHi, uint32_t aLo,
                                       uint32_t bHi, int lane) {
    const uint32_t aoff = ((lane & 7) + ((lane >> 3) & 1) * 8) * BROW + ((lane >> 4) & 1) * 16;
    const uint32_t boff = ((lane & 7) + ((lane >> 4) & 1) * 8) * BROW + ((lane >> 3) & 1) * 16;
#pragma unroll
    for (int ks = 0; ks < 8; ++ks) {
        uint32_t ah[4], al[4];
        ldm4(ah, aHi + aoff + ks * 32);
        ldm4(al, aLo + aoff + ks * 32);
#pragma unroll
        for (int p = 0; p < NT / 2; ++p) {
            uint32_t bh[4];
            ldm4(bh, bHi + p * 16 * BROW + boff + ks * 32);
            mma16816(acc[2 * p],     ah, bh[0], bh[1]);
            mma16816(acc[2 * p + 1], ah, bh[2], bh[3]);
            mma16816(acc[2 * p],     al, bh[0], bh[1]);
            mma16816(acc[2 * p + 1], al, bh[2], bh[3]);
        }
    }
}

__device__ __forceinline__ void splitst(char* smc, int row, int col, float v0, float v1) {
    __half h0 = __float2half(v0), h1 = __float2half(v1);
    __half2 hp; hp.x = h0; hp.y = h1;
    __half2 lp;
    lp.x = __float2half(v0 - __half2float(h0));
    lp.y = __float2half(v1 - __half2float(h1));
    int off = row * BROW + col * 2;
    *(__half2*)(smc + SA_HI + off) = hp;
    *(__half2*)(smc + SA_LO + off) = lp;
}
__device__ __forceinline__ void cpyB(uint32_t dst, const unsigned char* src, int bytes, int tid) {
    for (int i = tid * 16; i < bytes; i += 256 * 16) CP16(dst + i, src + i);
    CP_COMMIT();
}

// ---------------- per-node precompute: P1, P2, vel_scale ----------------
__global__ void __launch_bounds__(256, 2)
egnn_pre(const float* __restrict__ h, int N,
         const float* __restrict__ vb1, const float* __restrict__ vW2) {
    extern __shared__ __align__(16) char smc[];
    uint32_t sb = smem_u32(smc);
    const int tid = threadIdx.x, wid = tid >> 5, lane = tid & 31;
    float* cst = (float*)(smc + SCST);
    const int n0 = blockIdx.x * 128;

    cpyB(sb + SB, g_wimg + IMG_E1A, 34816, tid);
    if (tid < 128) { cst[tid] = __ldg(vb1 + tid); cst[128 + tid] = __ldg(vW2 + tid); }
    {   // load h rows (coalesced-ish) -> split A
        int row = wid * 16 + (lane >> 1);
        int n = n0 + row; if (n >= N) n = N - 1;
        int c0 = (lane & 1) * 64;
        const float4* src = (const float4*)(h + (size_t)n * 128 + c0);
#pragma unroll
        for (int q = 0; q < 16; ++q) {
            float4 f = __ldg(src + q);
            splitst(smc, row, c0 + q * 4, f.x, f.y);
            splitst(smc, row, c0 + q * 4 + 2, f.z, f.w);
        }
    }
    CP_WAIT(0); __syncthreads();

    const uint32_t aHi = sb + SA_HI + wid * 16 * BROW;
    const uint32_t aLo = sb + SA_LO + wid * 16 * BROW;
    const int r0 = wid * 16 + lane / 4, r1 = r0 + 8;
    float4 acc[16];
#pragma unroll
    for (int t = 0; t < 16; ++t) acc[t] = make_float4(0.f, 0.f, 0.f, 0.f);

    gemm2p<16>(acc, aHi, aLo, sb + SB, lane);          // P1 = h @ eW1a
    __syncthreads();
    cpyB(sb + SB, g_wimg + IMG_E1B, 34816, tid);
#pragma unroll
    for (int t = 0; t < 16; ++t) {
        int c = t * 8 + (lane & 3) * 2;
        if (n0 + r0 < N) *(float2*)(g_p1 + (size_t)(n0 + r0) * 128 + c) = make_float2(acc[t].x, acc[t].y);
        if (n0 + r1 < N) *(float2*)(g_p1 + (size_t)(n0 + r1) * 128 + c) = make_float2(acc[t].z, acc[t].w);
        acc[t] = make_float4(0.f, 0.f, 0.f, 0.f);
    }
    CP_WAIT(0); __syncthreads();

    gemm2p<16>(acc, aHi, aLo, sb + SB, lane);          // P2 = h @ eW1b
    __syncthreads();
    cpyB(sb + SB, g_wimg + IMG_V1, 34816, tid);
#pragma unroll
    for (int t = 0; t < 16; ++t) {
        int c = t * 8 + (lane & 3) * 2;
        if (n0 + r0 < N) *(float2*)(g_p2 + (size_t)(n0 + r0) * 128 + c) = make_float2(acc[t].x, acc[t].y);
        if (n0 + r1 < N) *(float2*)(g_p2 + (size_t)(n0 + r1) * 128 + c) = make_float2(acc[t].z, acc[t].w);
        acc[t] = make_float4(0.f, 0.f, 0.f, 0.f);
    }
    CP_WAIT(0); __syncthreads();

    gemm2p<16>(acc, aHi, aLo, sb + SB, lane);          // h @ vW1
    {
        float s0 = 0.f, s1 = 0.f;
#pragma unroll
        for (int t = 0; t < 16; ++t) {
            int c = t * 8 + (lane & 3) * 2;
            float b0 = cst[c], b1 = cst[c + 1];
            float w0 = cst[128 + c], w1 = cst[128 + c + 1];
            s0 += siluf(acc[t].x + b0) * w0 + siluf(acc[t].y + b1) * w1;
            s1 += siluf(acc[t].z + b0) * w0 + siluf(acc[t].w + b1) * w1;
        }
        s0 += __shfl_xor_sync(0xFFFFFFFF, s0, 1); s1 += __shfl_xor_sync(0xFFFFFFFF, s1, 1);
        s0 += __shfl_xor_sync(0xFFFFFFFF, s0, 2); s1 += __shfl_xor_sync(0xFFFFFFFF, s1, 2);
        if ((lane & 3) == 0) {
            if (n0 + r0 < N) g_vel[n0 + r0] = s0;
            if (n0 + r1 < N) g_vel[n0 + r1] = s1;
        }
    }
}

// ---------------- edge kernel ----------------
__global__ void __launch_bounds__(256, 2)
egnn_edge_mma(const float* __restrict__ x, const float* __restrict__ eattr,
              const int* __restrict__ ei, int E,
              const float* __restrict__ eW1, const float* __restrict__ eb1,
              const float* __restrict__ eb2,
              const float* __restrict__ cb1, const float* __restrict__ cW2,
              const float* __restrict__ ib1, const float* __restrict__ iW2,
              const float* __restrict__ ib2) {
    extern __shared__ __align__(16) char smc[];
    uint32_t sb = smem_u32(smc);
    const int tid = threadIdx.x, wid = tid >> 5, lane = tid & 31;
    float* cst = (float*)(smc + SCST);
    float* xda = (float*)(smc + SXDA);
    int* ridx = (int*)(smc + SRIDX);
    int* cidx = (int*)(smc + SCIDX);
    const int e0 = blockIdx.x * 128;

    cpyB(sb + SB, g_wimg + IMG_E2, 34816, tid);

    if (tid < 128) {
        cst[tid]       = __ldg(eb1 + tid);
        cst[128 + tid] = __ldg(eb2 + tid);
        cst[256 + tid] = __ldg(cb1 + tid);
        cst[384 + tid] = __ldg(cW2 + tid);
        cst[512 + tid] = __ldg(eW1 + 256 * 128 + tid);
        cst[640 + tid] = __ldg(eW1 + 257 * 128 + tid);
        if (tid < 64) { cst[768 + tid] = __ldg(ib1 + tid); cst[832 + tid] = __ldg(iW2 + tid); }
        if (tid == 0) cst[896] = __ldg(ib2);
        int e = e0 + tid, r = 0, c = 0;
        float at = 0.f, valid = 0.f;
        if (e < E) { r = __ldg(ei + e); c = __ldg(ei + E + e); at = __ldg(eattr + e); valid = 1.f; }
        float dx = x[r * 3 + 0] - x[c * 3 + 0];
        float dy = x[r * 3 + 1] - x[c * 3 + 1];
        float dz = x[r * 3 + 2] - x[c * 3 + 2];
        xda[tid * 8 + 0] = dx; xda[tid * 8 + 1] = dy; xda[tid * 8 + 2] = dz;
        xda[tid * 8 + 3] = dx * dx + dy * dy + dz * dz;
        xda[tid * 8 + 4] = at; xda[tid * 8 + 7] = valid;
        ridx[tid] = r; cidx[tid] = c;
    }
    __syncthreads();

    // m1 = silu(P1[row] + P2[col] + dist*w256 + attr*w257 + b1) -> split A
    {
        int row = wid * 16 + (lane >> 1);
        int c0 = (lane & 1) * 64;
        const float4* p1 = (const float4*)(g_p1 + (size_t)ridx[row] * 128 + c0);
        const float4* p2 = (const float4*)(g_p2 + (size_t)cidx[row] * 128 + c0);
        float d = xda[row * 8 + 3], at = xda[row * 8 + 4];
#pragma unroll
        for (int q = 0; q < 16; ++q) {
            float4 f1 = __ldg(p1 + q), f2 = __ldg(p2 + q);
            int c = c0 + q * 4;
            float v0 = f1.x + f2.x + cst[c]     + d * cst[512 + c]     + at * cst[640 + c];
            float v1 = f1.y + f2.y + cst[c + 1] + d * cst[512 + c + 1] + at * cst[640 + c + 1];
            float v2 = f1.z + f2.z + cst[c + 2] + d * cst[512 + c + 2] + at * cst[640 + c + 2];
            float v3 = f1.w + f2.w + cst[c + 3] + d * cst[512 + c + 3] + at * cst[640 + c + 3];
            splitst(smc, row, c,     siluf(v0), siluf(v1));
            splitst(smc, row, c + 2, siluf(v2), siluf(v3));
        }
    }
    CP_WAIT(0); __syncthreads();           // B = eW2

    const uint32_t aHi = sb + SA_HI + wid * 16 * BROW;
    const uint32_t aLo = sb + SA_LO + wid * 16 * BROW;
    const int r0 = wid * 16 + lane / 4, r1 = r0 + 8;
    float4 acc[16];
#pragma unroll
    for (int t = 0; t < 16; ++t) acc[t] = make_float4(0.f, 0.f, 0.f, 0.f);

    // stage 2: m_ij = silu(m1 @ eW2 + b2) -> A
    gemm2p<16>(acc, aHi, aLo, sb + SB, lane);
    __syncthreads();
    cpyB(sb + SB, g_wimg + IMG_C1, 34816, tid);
#pragma unroll
    for (int t = 0; t < 16; ++t) {
        int c = t * 8 + (lane & 3) * 2;
        float b0 = cst[128 + c], b1 = cst[128 + c + 1];
        splitst(smc, r0, c, siluf(acc[t].x + b0), siluf(acc[t].y + b1));
        splitst(smc, r1, c, siluf(acc[t].z + b0), siluf(acc[t].w + b1));
        acc[t] = make_float4(0.f, 0.f, 0.f, 0.f);
    }
    CP_WAIT(0); __syncthreads();           // B = cW1

    // stage 3: phi = silu(m_ij @ cW1 + cb1) . cW2
    gemm2p<16>(acc, aHi, aLo, sb + SB, lane);
    __syncthreads();
    cpyB(sb + SB, g_wimg + IMG_I1, 17408, tid);
    {
        float p0 = 0.f, p1 = 0.f;
#pragma unroll
        for (int t = 0; t < 16; ++t) {
            int c = t * 8 + (lane & 3) * 2;
            float b0 = cst[256 + c], b1 = cst[256 + c + 1];
            float w0 = cst[384 + c], w1 = cst[384 + c + 1];
            p0 += siluf(acc[t].x + b0) * w0 + siluf(acc[t].y + b1) * w1;
            p1 += siluf(acc[t].z + b0) * w0 + siluf(acc[t].w + b1) * w1;
            acc[t] = make_float4(0.f, 0.f, 0.f, 0.f);
        }
        p0 += __shfl_xor_sync(0xFFFFFFFF, p0, 1); p1 += __shfl_xor_sync(0xFFFFFFFF, p1, 1);
        p0 += __shfl_xor_sync(0xFFFFFFFF, p0, 2); p1 += __shfl_xor_sync(0xFFFFFFFF, p1, 2);
        if ((lane & 3) == 0) { xda[r0 * 8 + 6] = p0; xda[r1 * 8 + 6] = p1; }
    }
    CP_WAIT(0); __syncthreads();           // B = iW1

    // stage 4: e = sigmoid(silu(m_ij @ iW1 + ib1) . iW2 + ib2)
    gemm2p<8>(acc, aHi, aLo, sb + SB, lane);
    {
        float s0 = 0.f, s1 = 0.f;
#pragma unroll
        for (int t = 0; t < 8; ++t) {
            int c = t * 8 + (lane & 3) * 2;
            float b0 = cst[768 + c], b1 = cst[768 + c + 1];
            float w0 = cst[832 + c], w1 = cst[832 + c + 1];
            s0 += siluf(acc[t].x + b0) * w0 + siluf(acc[t].y + b1) * w1;
            s1 += siluf(acc[t].z + b0) * w0 + siluf(acc[t].w + b1) * w1;
        }
        s0 += __shfl_xor_sync(0xFFFFFFFF, s0, 1); s1 += __shfl_xor_sync(0xFFFFFFFF, s1, 1);
        s0 += __shfl_xor_sync(0xFFFFFFFF, s0, 2); s1 += __shfl_xor_sync(0xFFFFFFFF, s1, 2);
        float bi = cst[896];
        if ((lane & 3) == 0) { xda[r0 * 8 + 5] = fsig(s0 + bi); xda[r1 * 8 + 5] = fsig(s1 + bi); }
    }
    __syncthreads();

    // ---- scatter ----
    if (tid < 128 && xda[tid * 8 + 7] != 0.f) {
        float s = xda[tid * 8 + 5] * xda[tid * 8 + 6];
        atomicAdd(&g_agg[ridx[tid]],
                  make_float4(s * xda[tid * 8 + 0], s * xda[tid * 8 + 1],
                              s * xda[tid * 8 + 2], 1.0f));
    }
    for (int q = tid; q < 128 * 32; q += 256) {
        int t = q >> 5, k4 = q & 31;
        if (xda[t * 8 + 7] == 0.f) continue;
        float e = xda[t * 8 + 5];
        int off = t * BROW + k4 * 8;
        __half2 h0 = *(__half2*)(smc + SA_HI + off);
        __half2 h1 = *(__half2*)(smc + SA_HI + off + 4);
        __half2 l0 = *(__half2*)(smc + SA_LO + off);
        __half2 l1 = *(__half2*)(smc + SA_LO + off + 4);
        float4 m;
        m.x = (__half2float(h0.x) + __half2float(l0.x)) * e;
        m.y = (__half2float(h0.y) + __half2float(l0.y)) * e;
        m.z = (__half2float(h1.x) + __half2float(l1.x)) * e;
        m.w = (__half2float(h1.y) + __half2float(l1.y)) * e;
        atomicAdd(((float4*)g_mi) + (size_t)ridx[t] * 32 + k4, m);
    }
}

// ---------------- node kernel (scalar fp32; vel comes from g_vel) ----------------
#define TEN 64
#define LDN 132
#define NO_A 0
#define NO_B (TEN * LDN)
#define NO_C (2 * TEN * LDN)
#define NO_W (3 * TEN * LDN)
#define ND_SMEM ((NO_W + 1024 + 64) * 4)

__device__ __forceinline__ void nd_init(float acc[4][8], const float* __restrict__ bias, int tx) {
    float4 b0 = __ldg((const float4*)bias + tx * 2);
    float4 b1 = __ldg((const float4*)bias + tx * 2 + 1);
#pragma unroll
    for (int i = 0; i < 4; ++i) {
        acc[i][0] = b0.x; acc[i][1] = b0.y; acc[i][2] = b0.z; acc[i][3] = b0.w;
        acc[i][4] = b1.x; acc[i][5] = b1.y; acc[i][6] = b1.z; acc[i][7] = b1.w;
    }
}
__device__ __forceinline__ void nd_gemm(float acc[4][8], const float* __restrict__ As,
                                        const float* __restrict__ Wg, int K,
                                        float* wt, int tid, int ty, int tx) {
    for (int k0 = 0; k0 < K; k0 += 8) {
        __syncthreads();
        ((float4*)wt)[tid] = __ldg((const float4*)(Wg + k0 * 128) + tid);
        __syncthreads();
        const float* ap = As + (ty * 4) * LDN + k0;
#pragma unroll
        for (int k = 0; k < 8; ++k) {
            float a[4] = {ap[k], ap[LDN + k], ap[2 * LDN + k], ap[3 * LDN + k]};
            float4 b0 = *(const float4*)(wt + k * 128 + tx * 8);
            float4 b1 = *(const float4*)(wt + k * 128 + tx * 8 + 4);
            float b[8] = {b0.x, b0.y, b0.z, b0.w, b1.x, b1.y, b1.z, b1.w};
#pragma unroll
            for (int i = 0; i < 4; ++i)
#pragma unroll
                for (int j = 0; j < 8; ++j) acc[i][j] += a[i] * b[j];
        }
    }
}
template <bool ACT>
__device__ __forceinline__ void nd_store(const float acc[4][8], float* C, int ty, int tx) {
#pragma unroll
    for (int i = 0; i < 4; ++i) {
        float4 v0, v1;
        v0.x = ACT ? siluf(acc[i][0]) : acc[i][0]; v0.y = ACT ? siluf(acc[i][1]) : acc[i][1];
        v0.z = ACT ? siluf(acc[i][2]) : acc[i][2]; v0.w = ACT ? siluf(acc[i][3]) : acc[i][3];
        v1.x = ACT ? siluf(acc[i][4]) : acc[i][4]; v1.y = ACT ? siluf(acc[i][5]) : acc[i][5];
        v1.z = ACT ? siluf(acc[i][6]) : acc[i][6]; v1.w = ACT ? siluf(acc[i][7]) : acc[i][7];
        float* p = C + (ty * 4 + i) * LDN + tx * 8;
        *(float4*)p = v0; *(float4*)(p + 4) = v1;
    }
}
__global__ void __launch_bounds__(256, 2)
egnn_node_kernel(const float* __restrict__ h, const float* __restrict__ x,
                 const float* __restrict__ vinit, int N,
                 const float* __restrict__ nW1, const float* __restrict__ nb1,
                 const float* __restrict__ nW2, const float* __restrict__ nb2,
                 float* __restrict__ out_h, float* __restrict__ out_x, float* __restrict__ out_v) {
    extern __shared__ float smf[];
    float* bufA = smf + NO_A; float* bufB = smf + NO_B;
    float* bufC = smf + NO_C; float* wt = smf + NO_W;
    const int tid = threadIdx.x, tx = tid & 15, ty = tid >> 4;
    const int n0 = blockIdx.x * TEN;
    for (int q = tid; q < TEN * 32; q += 256) {
        int t = q >> 5, k4 = q & 31, n = n0 + t;
        if (n >= N) n = N - 1;
        ((float4*)(bufA + t * LDN))[k4] = __ldg((const float4*)h + n * 32 + k4);
        ((float4*)(bufB + t * LDN))[k4] = ((const float4*)g_mi)[n * 32 + k4];
    }
    // v_out / x_out epilogue from precomputed vel_scale + aggregates
    if (tid < TEN) {
        int n = n0 + tid;
        if (n < N) {
            float s = g_vel[n];
            float vx = vinit[n * 3 + 0] * s, vy = vinit[n * 3 + 1] * s, vz = vinit[n * 3 + 2] * s;
            out_v[n * 3 + 0] = vx; out_v[n * 3 + 1] = vy; out_v[n * 3 + 2] = vz;
            float4 ag = g_agg[n];
            float inv = 1.0f / (float)(N - 1);
            float x0 = x[n * 3 + 0], x1 = x[n * 3 + 1], x2 = x[n * 3 + 2];
            if (ag.w > 0.f) {
                out_x[n * 3 + 0] = x0 + vx + ag.x * inv;
                out_x[n * 3 + 1] = x1 + vy + ag.y * inv;
                out_x[n * 3 + 2] = x2 + vz + ag.z * inv;
            } else {
                out_x[n * 3 + 0] = x0; out_x[n * 3 + 1] = x1; out_x[n * 3 + 2] = x2;
            }
        }
    }
    float acc[4][8];
    nd_init(acc, nb1, tx);
    nd_gemm(acc, bufA, nW1, 128, wt, tid, ty, tx);
    nd_gemm(acc, bufB, nW1 + 128 * 128, 128, wt, tid, ty, tx);
    nd_store<true>(acc, bufC, ty, tx);
    nd_init(acc, nb2, tx);
    nd_gemm(acc, bufC, nW2, 128, wt, tid, ty, tx);
#pragma unroll
    for (int i = 0; i < 4; ++i) {
        int n = n0 + ty * 4 + i;
        if (n < N) {
            float4* p = (float4*)(out_h + (size_t)n * 128);
            p[tx * 2]     = make_float4(acc[i][0], acc[i][1], acc[i][2], acc[i][3]);
            p[tx * 2 + 1] = make_float4(acc[i][4], acc[i][5], acc[i][6], acc[i][7]);
        }
    }
}

extern "C" void kernel_launch(void* const* d_in, const int* in_sizes, int n_in,
                              void* d_out, int out_size) {
    const float* h     = (const float*)d_in[0];
    const float* x     = (const float*)d_in[1];
    const float* eattr = (const float*)d_in[2];
    const float* vinit = (const float*)d_in[3];
    const int*   ei    = (const int*)d_in[4];
    const float* eW1 = (const float*)d_in[5];
    const float* eb1 = (const float*)d_in[6];
    const float* eW2 = (const float*)d_in[7];
    const float* eb2 = (const float*)d_in[8];
    const float* cW1 = (const float*)d_in[9];
    const float* cb1 = (const float*)d_in[10];
    const float* cW2 = (const float*)d_in[11];
    const float* iW1 = (const float*)d_in[12];
    const float* ib1 = (const float*)d_in[13];
    const float* iW2 = (const float*)d_in[14];
    const float* ib2 = (const float*)d_in[15];
    const float* nW1 = (const float*)d_in[16];
    const float* nb1 = (const float*)d_in[17];
    const float* nW2 = (const float*)d_in[18];
    const float* nb2 = (const float*)d_in[19];
    const float* vW1 = (const float*)d_in[20];
    const float* vb1 = (const float*)d_in[21];
    const float* vW2 = (const float*)d_in[22];
    int N = in_sizes[0] / 128;
    int E = in_sizes[2];
    float* out   = (float*)d_out;
    float* out_h = out;
    float* out_x = out + (size_t)N * 128;
    float* out_v = out_x + (size_t)N * 3;

    cudaFuncSetAttribute(egnn_pre, cudaFuncAttributeMaxDynamicSharedMemorySize, E_SMEM);
    cudaFuncSetAttribute(egnn_edge_mma, cudaFuncAttributeMaxDynamicSharedMemorySize, E_SMEM);
    cudaFuncSetAttribute(egnn_node_kernel, cudaFuncAttributeMaxDynamicSharedMemorySize, ND_SMEM);

    prep_weights<<<352, 256>>>(eW1, eW2, cW1, iW1, vW1);
    egnn_zero_kernel<<<512, 256>>>(N);
    egnn_pre<<<(N + 127) / 128, 256, E_SMEM>>>(h, N, vb1, vW2);
    egnn_edge_mma<<<(E + 127) / 128, 256, E_SMEM>>>(
        x, eattr, ei, E, eW1, eb1, eb2, cb1, cW2, ib1, iW2, ib2);
    egnn_node_kernel<<<(N + TEN - 1) / TEN, 256, ND_SMEM>>>(
        h, x, vinit, N, nW1, nb1, nW2, nb2, out_h, out_x, out_v);
}

// round 15
// speedup vs baseline: 1.3902x; 1.3902x over previous
#include <cuda_runtime.h>
#include <cuda_fp16.h>
#include <cstdint>

// ===========================================================================
// EGNN layer. Edge + node MLPs on mma.sync fp16.
// Stages feeding h_out (edge 1,2; node) use 2-pass hi/lo split (~1e-4 err);
// stages feeding only scalars phi/e (edge 3,4) use single-pass fp16.
// (Resubmission of R8 — previous round was a container-level infra failure.)
// ===========================================================================

#define MAXN 50016
__device__ float  g_mi[(size_t)MAXN * 128];
__device__ float4 g_agg[MAXN];
// fp16 W^T images, row stride 272B
__device__ __align__(16) unsigned char g_wimg[295936];
#define IMG_E1A 0
#define IMG_E1B 34816
#define IMG_E2  69632
#define IMG_C1  104448
#define IMG_I1  139264
#define IMG_V1  156672
#define IMG_N1A 191488
#define IMG_N1B 226304
#define IMG_N2  261120
#define BROW    272

// ---- smem layout (bytes), 113280 total -> 2 CTAs/SM ----
#define SA_HI   0
#define SA_LO   34816
#define SB      69632
#define SCST    104448       // 928 floats
#define SXDA    108160       // 128*8 floats
#define SRIDX   112256
#define SCIDX   112768
#define E_SMEM  113280

__device__ __forceinline__ uint32_t smem_u32(const void* p) {
    uint32_t a;
    asm("{ .reg .u64 t; cvta.to.shared.u64 t, %1; cvt.u32.u64 %0, t; }" : "=r"(a) : "l"(p));
    return a;
}
__device__ __forceinline__ void ldm4(uint32_t r[4], uint32_t addr) {
    asm volatile("ldmatrix.sync.aligned.m8n8.x4.shared.b16 {%0,%1,%2,%3}, [%4];"
        : "=r"(r[0]), "=r"(r[1]), "=r"(r[2]), "=r"(r[3]) : "r"(addr));
}
__device__ __forceinline__ void mma16816(float4& d, const uint32_t a[4], uint32_t b0, uint32_t b1) {
    asm volatile("mma.sync.aligned.m16n8k16.row.col.f32.f16.f16.f32 "
        "{%0,%1,%2,%3}, {%4,%5,%6,%7}, {%8,%9}, {%0,%1,%2,%3};"
        : "+f"(d.x), "+f"(d.y), "+f"(d.z), "+f"(d.w)
        : "r"(a[0]), "r"(a[1]), "r"(a[2]), "r"(a[3]), "r"(b0), "r"(b1));
}
#define CP16(dst, src) \
    asm volatile("cp.async.cg.shared.global [%0], [%1], 16;" :: "r"(dst), "l"(src))
#define CP_COMMIT() asm volatile("cp.async.commit_group;" ::: "memory")
#define CP_WAIT(n)  asm volatile("cp.async.wait_group %0;" :: "n"(n) : "memory")

// ---- MUFU-free silu ----
__device__ __forceinline__ float fexp_neg(float v) {
    float t = fminf(fmaxf(v, -30.f), 30.f) * -1.44269504f;
    float r = t + 12582912.f;
    int   k = __float_as_int(r) - 0x4B400000;
    float f = t - (r - 12582912.f);
    float g = f * 0.69314718f;
    float p = 1.f + g * (1.f + g * (0.5f + g * (0.16666667f + g * (0.041666667f
            + g * (8.3333333e-3f + g * 1.3888889e-3f)))));
    return p * __int_as_float((k + 127) << 23);
}
__device__ __forceinline__ float frcp(float d) {
    float y = __int_as_float(0x7EF311C3 - __float_as_int(d));
    y = y * (2.f - d * y); y = y * (2.f - d * y); y = y * (2.f - d * y);
    return y;
}
__device__ __forceinline__ float fsig(float v)  { return frcp(1.f + fexp_neg(v)); }
__device__ __forceinline__ float siluf(float v) { return v * fsig(v); }

__global__ void prep_weights(const float* __restrict__ eW1, const float* __restrict__ eW2,
                             const float* __restrict__ cW1, const float* __restrict__ iW1,
                             const float* __restrict__ vW1, const float* __restrict__ nW1,
                             const float* __restrict__ nW2) {
    int i = blockIdx.x * blockDim.x + threadIdx.x;
    int base, n, k; float w;
    if (i < 16384) {
        k = i >> 7; n = i & 127; base = IMG_E1A; w = eW1[k * 128 + n];
    } else if (i < 32768) {
        int j = i - 16384; k = j >> 7; n = j & 127; base = IMG_E1B; w = eW1[(128 + k) * 128 + n];
    } else if (i < 49152) {
        int j = i - 32768; k = j >> 7; n = j & 127; base = IMG_E2; w = eW2[k * 128 + n];
    } else if (i < 65536) {
        int j = i - 49152; k = j >> 7; n = j & 127; base = IMG_C1; w = cW1[k * 128 + n];
    } else if (i < 73728) {
        int j = i - 65536; k = j >> 6; n = j & 63; base = IMG_I1; w = iW1[k * 64 + n];
    } else if (i < 90112) {
        int j = i - 73728; k = j >> 7; n = j & 127; base = IMG_V1; w = vW1[k * 128 + n];
    } else if (i < 106496) {
        int j = i - 90112; k = j >> 7; n = j & 127; base = IMG_N1A; w = nW1[k * 128 + n];
    } else if (i < 122880) {
        int j = i - 106496; k = j >> 7; n = j & 127; base = IMG_N1B; w = nW1[(128 + k) * 128 + n];
    } else if (i < 139264) {
        int j = i - 122880; k = j >> 7; n = j & 127; base = IMG_N2; w = nW2[k * 128 + n];
    } else return;
    *(__half*)(g_wimg + base + n * BROW + k * 2) = __float2half(w);
}

__global__ void egnn_zero_kernel(int N) {
    int total = N * 32;
    for (int i = blockIdx.x * blockDim.x + threadIdx.x; i < total + N; i += gridDim.x * blockDim.x) {
        if (i < total) ((float4*)g_mi)[i] = make_float4(0.f, 0.f, 0.f, 0.f);
        else           g_agg[i - total]   = make_float4(0.f, 0.f, 0.f, 0.f);
    }
}

// 2-pass split GEMM: acc[NT] += (Ahi+Alo)[16,128] @ B[128, NT*8]
template <int NT>
__device__ __forceinline__ void gemm2p(float4* acc, uint32_t aHi, uint32_t aLo,
                                       uint32_t bHi, int lane) {
    const uint32_t aoff = ((lane & 7) + ((lane >> 3) & 1) * 8) * BROW + ((lane >> 4) & 1) * 16;
    const uint32_t boff = ((lane & 7) + ((lane >> 4) & 1) * 8) * BROW + ((lane >> 3) & 1) * 16;
#pragma unroll
    for (int ks = 0; ks < 8; ++ks) {
        uint32_t ah[4], al[4];
        ldm4(ah, aHi + aoff + ks * 32);
        ldm4(al, aLo + aoff + ks * 32);
#pragma unroll
        for (int p = 0; p < NT / 2; ++p) {
            uint32_t bh[4];
            ldm4(bh, bHi + p * 16 * BROW + boff + ks * 32);
            mma16816(acc[2 * p],     ah, bh[0], bh[1]);
            mma16816(acc[2 * p + 1], ah, bh[2], bh[3]);
            mma16816(acc[2 * p],     al, bh[0], bh[1]);
            mma16816(acc[2 * p + 1], al, bh[2], bh[3]);
        }
    }
}
// 1-pass fp16 GEMM (hi only) — for stages feeding scalars phi / e
template <int NT>
__device__ __forceinline__ void gemm1p(float4* acc, uint32_t aHi, uint32_t bHi, int lane) {
    const uint32_t aoff = ((lane & 7) + ((lane >> 3) & 1) * 8) * BROW + ((lane >> 4) & 1) * 16;
    const uint32_t boff = ((lane & 7) + ((lane >> 4) & 1) * 8) * BROW + ((lane >> 3) & 1) * 16;
#pragma unroll
    for (int ks = 0; ks < 8; ++ks) {
        uint32_t ah[4];
        ldm4(ah, aHi + aoff + ks * 32);
#pragma unroll
        for (int p = 0; p < NT / 2; ++p) {
            uint32_t bh[4];
            ldm4(bh, bHi + p * 16 * BROW + boff + ks * 32);
            mma16816(acc[2 * p],     ah, bh[0], bh[1]);
            mma16816(acc[2 * p + 1], ah, bh[2], bh[3]);
        }
    }
}

__device__ __forceinline__ void splitst(char* smc, int row, int col, float v0, float v1) {
    __half h0 = __float2half(v0), h1 = __float2half(v1);
    __half2 hp; hp.x = h0; hp.y = h1;
    __half2 lp;
    lp.x = __float2half(v0 - __half2float(h0));
    lp.y = __float2half(v1 - __half2float(h1));
    int off = row * BROW + col * 2;
    *(__half2*)(smc + SA_HI + off) = hp;
    *(__half2*)(smc + SA_LO + off) = lp;
}
__device__ __forceinline__ void gatherA(char* smc, const float* __restrict__ src0,
                                        const int* idx, int wid, int lane) {
    int row = wid * 16 + (lane >> 1);
    int c0 = (lane & 1) * 64;
    const float4* src = (const float4*)(src0 + (size_t)idx[row] * 128 + c0);
#pragma unroll
    for (int q = 0; q < 16; ++q) {
        float4 f = __ldg(src + q);
        splitst(smc, row, c0 + q * 4, f.x, f.y);
        splitst(smc, row, c0 + q * 4 + 2, f.z, f.w);
    }
}
__device__ __forceinline__ void gatherRow(char* smc, const float* __restrict__ src0,
                                          int n, int wid, int lane) {
    int row = wid * 16 + (lane >> 1);
    int c0 = (lane & 1) * 64;
    const float4* src = (const float4*)(src0 + (size_t)n * 128 + c0);
#pragma unroll
    for (int q = 0; q < 16; ++q) {
        float4 f = __ldg(src + q);
        splitst(smc, row, c0 + q * 4, f.x, f.y);
        splitst(smc, row, c0 + q * 4 + 2, f.z, f.w);
    }
}
__device__ __forceinline__ void cpyB(uint32_t dst, const unsigned char* src, int bytes, int tid) {
    for (int i = tid * 16; i < bytes; i += 256 * 16) CP16(dst + i, src + i);
    CP_COMMIT();
}

// ---------------- edge kernel ----------------
__global__ void __launch_bounds__(256, 2)
egnn_edge_mma(const float* __restrict__ h, const float* __restrict__ x,
              const float* __restrict__ eattr, const int* __restrict__ ei, int E,
              const float* __restrict__ eW1, const float* __restrict__ eb1,
              const float* __restrict__ eb2,
              const float* __restrict__ cb1, const float* __restrict__ cW2,
              const float* __restrict__ ib1, const float* __restrict__ iW2,
              const float* __restrict__ ib2) {
    extern __shared__ __align__(16) char smc[];
    uint32_t sb = smem_u32(smc);
    const int tid = threadIdx.x, wid = tid >> 5, lane = tid & 31;
    float* cst = (float*)(smc + SCST);
    float* xda = (float*)(smc + SXDA);
    int* ridx = (int*)(smc + SRIDX);
    int* cidx = (int*)(smc + SCIDX);
    const int e0 = blockIdx.x * 128;

    cpyB(sb + SB, g_wimg + IMG_E1A, 34816, tid);

    if (tid < 128) {
        cst[tid]       = __ldg(eb1 + tid);
        cst[128 + tid] = __ldg(eb2 + tid);
        cst[256 + tid] = __ldg(cb1 + tid);
        cst[384 + tid] = __ldg(cW2 + tid);
        cst[512 + tid] = __ldg(eW1 + 256 * 128 + tid);
        cst[640 + tid] = __ldg(eW1 + 257 * 128 + tid);
        if (tid < 64) { cst[768 + tid] = __ldg(ib1 + tid); cst[832 + tid] = __ldg(iW2 + tid); }
        if (tid == 0) cst[896] = __ldg(ib2);
        int e = e0 + tid, r = 0, c = 0;
        float at = 0.f, valid = 0.f;
        if (e < E) { r = __ldg(ei + e); c = __ldg(ei + E + e); at = __ldg(eattr + e); valid = 1.f; }
        float dx = x[r * 3 + 0] - x[c * 3 + 0];
        float dy = x[r * 3 + 1] - x[c * 3 + 1];
        float dz = x[r * 3 + 2] - x[c * 3 + 2];
        xda[tid * 8 + 0] = dx; xda[tid * 8 + 1] = dy; xda[tid * 8 + 2] = dz;
        xda[tid * 8 + 3] = dx * dx + dy * dy + dz * dz;
        xda[tid * 8 + 4] = at; xda[tid * 8 + 7] = valid;
        ridx[tid] = r; cidx[tid] = c;
    }
    __syncthreads();
    gatherA(smc, h, ridx, wid, lane);      // A = h[row]
    CP_WAIT(0); __syncthreads();           // B = eW1a

    const uint32_t aHi = sb + SA_HI + wid * 16 * BROW;
    const uint32_t aLo = sb + SA_LO + wid * 16 * BROW;
    const int r0 = wid * 16 + lane / 4, r1 = r0 + 8;
    float4 acc[16];
#pragma unroll
    for (int t = 0; t < 16; ++t) acc[t] = make_float4(0.f, 0.f, 0.f, 0.f);

    // stage 1a: h[row] @ eW1a
    gemm2p<16>(acc, aHi, aLo, sb + SB, lane);
    __syncthreads();
    cpyB(sb + SB, g_wimg + IMG_E1B, 34816, tid);
    gatherA(smc, h, cidx, wid, lane);      // A = h[col]
    CP_WAIT(0); __syncthreads();

    // stage 1b: + h[col] @ eW1b; tail + bias + silu -> m1 -> A
    gemm2p<16>(acc, aHi, aLo, sb + SB, lane);
    __syncthreads();
    cpyB(sb + SB, g_wimg + IMG_E2, 34816, tid);
    {
        float d0 = xda[r0 * 8 + 3], a0 = xda[r0 * 8 + 4];
        float d1 = xda[r1 * 8 + 3], a1 = xda[r1 * 8 + 4];
#pragma unroll
        for (int t = 0; t < 16; ++t) {
            int c = t * 8 + (lane & 3) * 2;
            float b0 = cst[c], b1 = cst[c + 1];
            float wA0 = cst[512 + c], wA1 = cst[512 + c + 1];
            float wB0 = cst[640 + c], wB1 = cst[640 + c + 1];
            splitst(smc, r0, c, siluf(acc[t].x + b0 + d0 * wA0 + a0 * wB0),
                                siluf(acc[t].y + b1 + d0 * wA1 + a0 * wB1));
            splitst(smc, r1, c, siluf(acc[t].z + b0 + d1 * wA0 + a1 * wB0),
                                siluf(acc[t].w + b1 + d1 * wA1 + a1 * wB1));
            acc[t] = make_float4(0.f, 0.f, 0.f, 0.f);
        }
    }
    CP_WAIT(0); __syncthreads();           // B = eW2

    // stage 2: m_ij = silu(m1 @ eW2 + b2) -> A
    gemm2p<16>(acc, aHi, aLo, sb + SB, lane);
    __syncthreads();
    cpyB(sb + SB, g_wimg + IMG_C1, 34816, tid);
#pragma unroll
    for (int t = 0; t < 16; ++t) {
        int c = t * 8 + (lane & 3) * 2;
        float b0 = cst[128 + c], b1 = cst[128 + c + 1];
        splitst(smc, r0, c, siluf(acc[t].x + b0), siluf(acc[t].y + b1));
        splitst(smc, r1, c, siluf(acc[t].z + b0), siluf(acc[t].w + b1));
        acc[t] = make_float4(0.f, 0.f, 0.f, 0.f);
    }
    CP_WAIT(0); __syncthreads();           // B = cW1

    // stage 3 (1-pass): phi = silu(m_ij @ cW1 + cb1) . cW2
    gemm1p<16>(acc, aHi, sb + SB, lane);
    __syncthreads();
    cpyB(sb + SB, g_wimg + IMG_I1, 17408, tid);
    {
        float p0 = 0.f, p1 = 0.f;
#pragma unroll
        for (int t = 0; t < 16; ++t) {
            int c = t * 8 + (lane & 3) * 2;
            float b0 = cst[256 + c], b1 = cst[256 + c + 1];
            float w0 = cst[384 + c], w1 = cst[384 + c + 1];
            p0 += siluf(acc[t].x + b0) * w0 + siluf(acc[t].y + b1) * w1;
            p1 += siluf(acc[t].z + b0) * w0 + siluf(acc[t].w + b1) * w1;
            acc[t] = make_float4(0.f, 0.f, 0.f, 0.f);
        }
        p0 += __shfl_xor_sync(0xFFFFFFFF, p0, 1); p1 += __shfl_xor_sync(0xFFFFFFFF, p1, 1);
        p0 += __shfl_xor_sync(0xFFFFFFFF, p0, 2); p1 += __shfl_xor_sync(0xFFFFFFFF, p1, 2);
        if ((lane & 3) == 0) { xda[r0 * 8 + 6] = p0; xda[r1 * 8 + 6] = p1; }
    }
    CP_WAIT(0); __syncthreads();           // B = iW1

    // stage 4 (1-pass): e = sigmoid(silu(m_ij @ iW1 + ib1) . iW2 + ib2)
    gemm1p<8>(acc, aHi, sb + SB, lane);
    {
        float s0 = 0.f, s1 = 0.f;
#pragma unroll
        for (int t = 0; t < 8; ++t) {
            int c = t * 8 + (lane & 3) * 2;
            float b0 = cst[768 + c], b1 = cst[768 + c + 1];
            float w0 = cst[832 + c], w1 = cst[832 + c + 1];
            s0 += siluf(acc[t].x + b0) * w0 + siluf(acc[t].y + b1) * w1;
            s1 += siluf(acc[t].z + b0) * w0 + siluf(acc[t].w + b1) * w1;
        }
        s0 += __shfl_xor_sync(0xFFFFFFFF, s0, 1); s1 += __shfl_xor_sync(0xFFFFFFFF, s1, 1);
        s0 += __shfl_xor_sync(0xFFFFFFFF, s0, 2); s1 += __shfl_xor_sync(0xFFFFFFFF, s1, 2);
        float bi = cst[896];
        if ((lane & 3) == 0) { xda[r0 * 8 + 5] = fsig(s0 + bi); xda[r1 * 8 + 5] = fsig(s1 + bi); }
    }
    __syncthreads();

    // ---- scatter ----
    if (tid < 128 && xda[tid * 8 + 7] != 0.f) {
        float s = xda[tid * 8 + 5] * xda[tid * 8 + 6];
        atomicAdd(&g_agg[ridx[tid]],
                  make_float4(s * xda[tid * 8 + 0], s * xda[tid * 8 + 1],
                              s * xda[tid * 8 + 2], 1.0f));
    }
    for (int q = tid; q < 128 * 32; q += 256) {
        int t = q >> 5, k4 = q & 31;
        if (xda[t * 8 + 7] == 0.f) continue;
        float e = xda[t * 8 + 5];
        int off = t * BROW + k4 * 8;
        __half2 h0 = *(__half2*)(smc + SA_HI + off);
        __half2 h1 = *(__half2*)(smc + SA_HI + off + 4);
        __half2 l0 = *(__half2*)(smc + SA_LO + off);
        __half2 l1 = *(__half2*)(smc + SA_LO + off + 4);
        float4 m;
        m.x = (__half2float(h0.x) + __half2float(l0.x)) * e;
        m.y = (__half2float(h0.y) + __half2float(l0.y)) * e;
        m.z = (__half2float(h1.x) + __half2float(l1.x)) * e;
        m.w = (__half2float(h1.y) + __half2float(l1.y)) * e;
        atomicAdd(((float4*)g_mi) + (size_t)ridx[t] * 32 + k4, m);
    }
}

// ---------------- node kernel (fp16 mma, 128 nodes/CTA) ----------------
__global__ void __launch_bounds__(256, 2)
egnn_node_mma(const float* __restrict__ h, const float* __restrict__ x,
              const float* __restrict__ vinit, int N,
              const float* __restrict__ nb1, const float* __restrict__ nb2,
              const float* __restrict__ vb1, const float* __restrict__ vW2,
              float* __restrict__ out_h, float* __restrict__ out_x,
              float* __restrict__ out_v) {
    extern __shared__ __align__(16) char smc[];
    uint32_t sb = smem_u32(smc);
    const int tid = threadIdx.x, wid = tid >> 5, lane = tid & 31;
    float* cst = (float*)(smc + SCST);
    float* xda = (float*)(smc + SXDA);
    const int n0 = blockIdx.x * 128;

    cpyB(sb + SB, g_wimg + IMG_V1, 34816, tid);
    if (tid < 128) {
        cst[tid]       = __ldg(nb1 + tid);
        cst[128 + tid] = __ldg(nb2 + tid);
        cst[256 + tid] = __ldg(vb1 + tid);
        cst[384 + tid] = __ldg(vW2 + tid);
    }
    {   // A = h rows n0..n0+127 (clamped)
        int row = wid * 16 + (lane >> 1);
        int n = n0 + row; if (n >= N) n = N - 1;
        gatherRow(smc, h, n, wid, lane);
    }
    CP_WAIT(0); __syncthreads();

    const uint32_t aHi = sb + SA_HI + wid * 16 * BROW;
    const uint32_t aLo = sb + SA_LO + wid * 16 * BROW;
    const int r0 = wid * 16 + lane / 4, r1 = r0 + 8;
    float4 acc[16];
#pragma unroll
    for (int t = 0; t < 16; ++t) acc[t] = make_float4(0.f, 0.f, 0.f, 0.f);

    // vel: s = silu(h @ vW1 + vb1) . vW2
    gemm2p<16>(acc, aHi, aLo, sb + SB, lane);
    __syncthreads();
    cpyB(sb + SB, g_wimg + IMG_N1A, 34816, tid);
    {
        float s0 = 0.f, s1 = 0.f;
#pragma unroll
        for (int t = 0; t < 16; ++t) {
            int c = t * 8 + (lane & 3) * 2;
            float b0 = cst[256 + c], b1 = cst[256 + c + 1];
            float w0 = cst[384 + c], w1 = cst[384 + c + 1];
            s0 += siluf(acc[t].x + b0) * w0 + siluf(acc[t].y + b1) * w1;
            s1 += siluf(acc[t].z + b0) * w0 + siluf(acc[t].w + b1) * w1;
            acc[t] = make_float4(0.f, 0.f, 0.f, 0.f);
        }
        s0 += __shfl_xor_sync(0xFFFFFFFF, s0, 1); s1 += __shfl_xor_sync(0xFFFFFFFF, s1, 1);
        s0 += __shfl_xor_sync(0xFFFFFFFF, s0, 2); s1 += __shfl_xor_sync(0xFFFFFFFF, s1, 2);
        if ((lane & 3) == 0) { xda[r0] = s0; xda[r1] = s1; }
    }
    CP_WAIT(0); __syncthreads();           // B = nW1a; vel in xda

    // x/v epilogue
    if (tid < 128) {
        int n = n0 + tid;
        if (n < N) {
            float s = xda[tid];
            float vx = vinit[n * 3 + 0] * s, vy = vinit[n * 3 + 1] * s, vz = vinit[n * 3 + 2] * s;
            out_v[n * 3 + 0] = vx; out_v[n * 3 + 1] = vy; out_v[n * 3 + 2] = vz;
            float4 ag = g_agg[n];
            float inv = 1.0f / (float)(N - 1);
            float x0 = x[n * 3 + 0], x1 = x[n * 3 + 1], x2 = x[n * 3 + 2];
            if (ag.w > 0.f) {
                out_x[n * 3 + 0] = x0 + vx + ag.x * inv;
                out_x[n * 3 + 1] = x1 + vy + ag.y * inv;
                out_x[n * 3 + 2] = x2 + vz + ag.z * inv;
            } else {
                out_x[n * 3 + 0] = x0; out_x[n * 3 + 1] = x1; out_x[n * 3 + 2] = x2;
            }
        }
    }

    // n1 part A: h @ nW1a
    gemm2p<16>(acc, aHi, aLo, sb + SB, lane);
    __syncthreads();
    cpyB(sb + SB, g_wimg + IMG_N1B, 34816, tid);
    {   // A = m_i rows
        int row = wid * 16 + (lane >> 1);
        int n = n0 + row; if (n >= N) n = N - 1;
        gatherRow(smc, g_mi, n, wid, lane);
    }
    CP_WAIT(0); __syncthreads();

    // n1 part B: + m_i @ nW1b; bias + silu -> A
    gemm2p<16>(acc, aHi, aLo, sb + SB, lane);
    __syncthreads();
    cpyB(sb + SB, g_wimg + IMG_N2, 34816, tid);
#pragma unroll
    for (int t = 0; t < 16; ++t) {
        int c = t * 8 + (lane & 3) * 2;
        float b0 = cst[c], b1 = cst[c + 1];
        splitst(smc, r0, c, siluf(acc[t].x + b0), siluf(acc[t].y + b1));
        splitst(smc, r1, c, siluf(acc[t].z + b0), siluf(acc[t].w + b1));
        acc[t] = make_float4(0.f, 0.f, 0.f, 0.f);
    }
    CP_WAIT(0); __syncthreads();           // B = nW2

    // h_out = n1 @ nW2 + nb2
    gemm2p<16>(acc, aHi, aLo, sb + SB, lane);
#pragma unroll
    for (int t = 0; t < 16; ++t) {
        int c = t * 8 + (lane & 3) * 2;
        float b0 = cst[128 + c], b1 = cst[128 + c + 1];
        if (n0 + r0 < N)
            *(float2*)(out_h + (size_t)(n0 + r0) * 128 + c) = make_float2(acc[t].x + b0, acc[t].y + b1);
        if (n0 + r1 < N)
            *(float2*)(out_h + (size_t)(n0 + r1) * 128 + c) = make_float2(acc[t].z + b0, acc[t].w + b1);
    }
}

extern "C" void kernel_launch(void* const* d_in, const int* in_sizes, int n_in,
                              void* d_out, int out_size) {
    const float* h     = (const float*)d_in[0];
    const float* x     = (const float*)d_in[1];
    const float* eattr = (const float*)d_in[2];
    const float* vinit = (const float*)d_in[3];
    const int*   ei    = (const int*)d_in[4];
    const float* eW1 = (const float*)d_in[5];
    const float* eb1 = (const float*)d_in[6];
    const float* eW2 = (const float*)d_in[7];
    const float* eb2 = (const float*)d_in[8];
    const float* cW1 = (const float*)d_in[9];
    const float* cb1 = (const float*)d_in[10];
    const float* cW2 = (const float*)d_in[11];
    const float* iW1 = (const float*)d_in[12];
    const float* ib1 = (const float*)d_in[13];
    const float* iW2 = (const float*)d_in[14];
    const float* ib2 = (const float*)d_in[15];
    const float* nW1 = (const float*)d_in[16];
    const float* nb1 = (const float*)d_in[17];
    const float* nW2 = (const float*)d_in[18];
    const float* nb2 = (const float*)d_in[19];
    const float* vW1 = (const float*)d_in[20];
    const float* vb1 = (const float*)d_in[21];
    const float* vW2 = (const float*)d_in[22];
    int N = in_sizes[0] / 128;
    int E = in_sizes[2];
    float* out   = (float*)d_out;
    float* out_h = out;
    float* out_x = out + (size_t)N * 128;
    float* out_v = out_x + (size_t)N * 3;

    cudaFuncSetAttribute(egnn_edge_mma, cudaFuncAttributeMaxDynamicSharedMemorySize, E_SMEM);
    cudaFuncSetAttribute(egnn_node_mma, cudaFuncAttributeMaxDynamicSharedMemorySize, E_SMEM);

    prep_weights<<<544, 256>>>(eW1, eW2, cW1, iW1, vW1, nW1, nW2);
    egnn_zero_kernel<<<512, 256>>>(N);
    egnn_edge_mma<<<(E + 127) / 128, 256, E_SMEM>>>(
        h, x, eattr, ei, E, eW1, eb1, eb2, cb1, cW2, ib1, iW2, ib2);
    egnn_node_mma<<<(N + 127) / 128, 256, E_SMEM>>>(
        h, x, vinit, N, nb1, nb2, vb1, vW2, out_h, out_x, out_v);
}